// round 13
// baseline (speedup 1.0000x reference)
#include <cuda_runtime.h>
#include <cuda_bf16.h>
#include <cstdint>

#define BB 4
#define HH 128
#define WW 128
#define HW (HH*WW)

typedef unsigned long long ull;
typedef unsigned short u16;

// ---------------- scratch ----------------
__device__ float g_flow_up[BB*2*HW];
__device__ float g_h3[BB*32*HW];
__device__ u16 g_f1h[BB*HW*128], g_f1l[BB*HW*128];
__device__ u16 g_f2h[BB*HW*128], g_f2l[BB*HW*128];
__device__ u16 g_c16h[BB*HW*64],  g_c16l[BB*HW*64];
__device__ u16 g_h1h[BB*HW*128],  g_h1l[BB*HW*128];
__device__ u16 g_h2h[BB*HW*64],   g_h2l[BB*HW*64];
__device__ u16 g_w1h[4*9*128*16], g_w1l[4*9*128*16];
__device__ u16 g_w2h[8*9*64*16],  g_w2l[8*9*64*16];
__device__ u16 g_w3h[4*9*32*16],  g_w3l[4*9*32*16];

// ---------------- helpers ----------------
__device__ __forceinline__ ull ffma2(ull a, ull b, ull c) {
    ull d;
    asm("fma.rn.f32x2 %0, %1, %2, %3;" : "=l"(d) : "l"(a), "l"(b), "l"(c));
    return d;
}
__device__ __forceinline__ ull pack2(float lo, float hi) {
    ull r;
    asm("mov.b64 %0, {%1, %2};" : "=l"(r) : "f"(lo), "f"(hi));
    return r;
}
__device__ __forceinline__ float2 unpack2(ull v) {
    float2 r;
    asm("mov.b64 {%0, %1}, %2;" : "=f"(r.x), "=f"(r.y) : "l"(v));
    return r;
}
__device__ __forceinline__ void cpasync16(uint32_t saddr, const void* g, bool v) {
    int sz = v ? 16 : 0;
    asm volatile("cp.async.cg.shared.global [%0], [%1], 16, %2;"
                 :: "r"(saddr), "l"(g), "r"(sz));
}
__device__ __forceinline__ void cpasync_commit() {
    asm volatile("cp.async.commit_group;");
}
__device__ __forceinline__ void cpasync_wait_all() {
    asm volatile("cp.async.wait_group 0;");
}
__device__ __forceinline__ uint32_t sptr(const void* p) {
    return (uint32_t)__cvta_generic_to_shared(p);
}
__device__ __forceinline__ void mma16816(float* c, const unsigned* a, unsigned b0, unsigned b1) {
    asm volatile(
        "mma.sync.aligned.m16n8k16.row.col.f32.bf16.bf16.f32 "
        "{%0,%1,%2,%3}, {%4,%5,%6,%7}, {%8,%9}, {%0,%1,%2,%3};"
        : "+f"(c[0]), "+f"(c[1]), "+f"(c[2]), "+f"(c[3])
        : "r"(a[0]), "r"(a[1]), "r"(a[2]), "r"(a[3]), "r"(b0), "r"(b1));
}
__device__ __forceinline__ void bf16split(float v, u16& h, u16& l) {
    __nv_bfloat16 hb = __float2bfloat16(v);
    float hf = __bfloat162float(hb);
    __nv_bfloat16 lb = __float2bfloat16(v - hf);
    h = *(u16*)&hb;
    l = *(u16*)&lb;
}

// ---------------- 0a) zero pad channels 49..63 of corr16 ----------------
__global__ void k_fillpad(u16* __restrict__ h, u16* __restrict__ l) {
    int idx = blockIdx.x*256 + threadIdx.x;
    if (idx >= BB*HW*15) return;
    int c = 49 + idx % 15;
    int p = idx / 15;
    h[(size_t)p*64 + c] = 0;
    l[(size_t)p*64 + c] = 0;
}

// ---------------- 0b) weight pre-split ----------------
template<int CIN, int OC>
__global__ void k_wsplit(const float* __restrict__ w, u16* __restrict__ wh, u16* __restrict__ wl) {
    constexpr int NCH = (CIN + 15)/16;
    int idx = blockIdx.x*256 + threadIdx.x;
    if (idx >= NCH*9*OC*16) return;
    int k  = idx & 15;
    int t2 = idx >> 4;
    int oc = t2 % OC;
    int t3 = t2 / OC;
    int s  = t3 % 9;
    int t  = t3 / 9;
    int ci = t*16 + k;
    float v = (ci < CIN) ? __ldg(w + ((size_t)oc*CIN + ci)*9 + s) : 0.f;
    u16 h, l;
    bf16split(v, h, l);
    wh[idx] = h; wl[idx] = l;
}

// ---------------- 0c) feature1 split (uint4-packed stores) ----------------
__global__ void k_f1split(const float* __restrict__ f, u16* __restrict__ fh, u16* __restrict__ fl) {
    int p = blockIdx.x*256 + threadIdx.x;
    if (p >= BB*HW) return;
    int b = p >> 14, pix = p & (HW-1);
    const float* src = f + (size_t)b*128*HW + pix;
    uint4* dh = (uint4*)(fh + (size_t)p*128);
    uint4* dl = (uint4*)(fl + (size_t)p*128);
    #pragma unroll 1
    for (int cg = 0; cg < 16; cg++) {
        u16 hh[8], ll[8];
        #pragma unroll
        for (int j = 0; j < 8; j++)
            bf16split(__ldg(src + (size_t)(cg*8 + j)*HW), hh[j], ll[j]);
        dh[cg] = *(uint4*)hh;
        dl[cg] = *(uint4*)ll;
    }
}

// ---------------- 1) grouped ConvTranspose2d ----------------
__global__ void k_upsample(const float* __restrict__ flow, const float* __restrict__ up_w,
                           float* __restrict__ out) {
    int idx = blockIdx.x * blockDim.x + threadIdx.x;
    if (idx >= BB*2*HW) return;
    int x = idx & 127;
    int y = (idx >> 7) & 127;
    int g = (idx >> 14) & 1;
    int b = idx >> 15;
    const float* fin = flow + (b*2 + g) * 64 * 64;
    const float* wg  = up_w + g * 16;
    float acc = 0.f;
    #pragma unroll
    for (int ky = 0; ky < 4; ky++) {
        int t = y + 1 - ky;
        if (t & 1) continue;
        int i = t >> 1;
        if ((unsigned)i >= 64u) continue;
        #pragma unroll
        for (int kx = 0; kx < 4; kx++) {
            int s = x + 1 - kx;
            if (s & 1) continue;
            int j = s >> 1;
            if ((unsigned)j >= 64u) continue;
            acc += fin[i*64 + j] * wg[ky*4 + kx];
        }
    }
    out[idx] = acc;
}

// ---------------- 2) warp feature2 -> channel-last bf16 hi/lo ----------------
__device__ __forceinline__ float reflectf(float v, float n) {
    float t = fmodf(fabsf(v), 2.0f * n);
    return n - fabsf(t - n);
}

__global__ void k_warp(const float* __restrict__ f2, const float* __restrict__ fu,
                       u16* __restrict__ fh, u16* __restrict__ fl) {
    int x = threadIdx.x;
    int y = blockIdx.x;
    int b = blockIdx.y;
    int c0 = blockIdx.z * 32;

    const float* fub = fu + (size_t)b*2*HW;
    float u0 = fub[y*WW + x];
    float u1 = fub[HW + y*WW + x];

    float fx = reflectf((float)x + 0.05f*u1, 127.f);
    float fy = reflectf((float)y + 0.05f*u0, 127.f);

    float x0f = floorf(fx), y0f = floorf(fy);
    float wx = fx - x0f, wy = fy - y0f;
    int x0 = min(max((int)x0f, 0), 127);
    int x1 = min(x0 + 1, 127);
    int y0 = min(max((int)y0f, 0), 127);
    int y1 = min(y0 + 1, 127);
    float w00 = (1.f-wx)*(1.f-wy), w01 = wx*(1.f-wy);
    float w10 = (1.f-wx)*wy,       w11 = wx*wy;

    int o00 = y0*WW + x0, o01 = y0*WW + x1, o10 = y1*WW + x0, o11 = y1*WW + x1;
    const float* fb = f2 + (size_t)b*128*HW;
    int po = y*WW + x;
    uint4* dh = (uint4*)(fh + ((size_t)b*HW + po)*128 + c0);
    uint4* dl = (uint4*)(fl + ((size_t)b*HW + po)*128 + c0);
    #pragma unroll 1
    for (int cg = 0; cg < 4; cg++) {
        u16 hh[8], ll[8];
        #pragma unroll
        for (int j = 0; j < 8; j++) {
            const float* fc = fb + (size_t)(c0 + cg*8 + j)*HW;
            float v = w00*fc[o00] + w01*fc[o01] + w10*fc[o10] + w11*fc[o11];
            bf16split(v, hh[j], ll[j]);
        }
        dh[cg] = *(uint4*)hh;
        dl[cg] = *(uint4*)ll;
    }
}

// ---------------- 3) MMA cost volume, 2-stage double-buffered ----------------
__global__ void __launch_bounds__(256) k_corrT(
    const u16* __restrict__ f1h_, const u16* __restrict__ f1l_,
    const u16* __restrict__ f2h_, const u16* __restrict__ f2l_,
    u16* __restrict__ ch16, u16* __restrict__ cl16)
{
    __shared__ __align__(16) u16 s1h[2][128*16], s1l[2][128*16];
    __shared__ __align__(16) u16 s2h[2][136*16], s2l[2][136*16];

    int tid = threadIdx.x;
    int y = blockIdx.x, dy = blockIdx.y, b = blockIdx.z;
    int wid = tid >> 5, lane = tid & 31;
    int g = lane >> 2, tg = lane & 3;
    int gy = y + dy - 3;
    bool rowok = (unsigned)gy < 128u;

    float acc[3][4];
    #pragma unroll
    for (int nf = 0; nf < 3; nf++)
        #pragma unroll
        for (int q = 0; q < 4; q++) acc[nf][q] = 0.f;

    size_t f1base = ((size_t)b*HW + y*WW)*128;
    size_t f2base = rowok ? ((size_t)b*HW + gy*WW)*128 : 0;

    auto stage = [&](int kc, int sb) {
        #pragma unroll
        for (int u = tid; u < 512; u += 256) {
            int half = u & 1;
            int px = (u >> 1) & 127;
            int arr = u >> 8;
            const u16* src = (arr ? f1l_ : f1h_) + f1base + (size_t)px*128 + kc*16 + half*8;
            u16* dst = (arr ? s1l[sb] : s1h[sb]) + px*16 + half*8;
            cpasync16(sptr(dst), src, true);
        }
        #pragma unroll
        for (int u = tid; u < 544; u += 256) {
            int half = u & 1;
            int idx = u >> 1;
            int qc = idx % 136;
            int arr = idx / 136;
            int q = qc - 3;
            bool v = rowok && (unsigned)q < 128u;
            const u16* src = (arr ? f2l_ : f2h_) + (v ? f2base + (size_t)q*128 + kc*16 + half*8 : 0);
            u16* dst = (arr ? s2l[sb] : s2h[sb]) + qc*16 + half*8;
            cpasync16(sptr(dst), src, v);
        }
        cpasync_commit();
    };

    stage(0, 0);

    #pragma unroll 1
    for (int kc = 0; kc < 8; kc++) {
        cpasync_wait_all();
        __syncthreads();
        if (kc + 1 < 8) stage(kc + 1, (kc + 1) & 1);
        int sb = kc & 1;

        int m0 = wid * 16;
        int abase = (m0 + g)*16 + 2*tg;
        unsigned ah[4], al[4];
        ah[0] = *(const unsigned*)(s1h[sb] + abase);
        ah[1] = *(const unsigned*)(s1h[sb] + abase + 8*16);
        ah[2] = *(const unsigned*)(s1h[sb] + abase + 8);
        ah[3] = *(const unsigned*)(s1h[sb] + abase + 8*16 + 8);
        al[0] = *(const unsigned*)(s1l[sb] + abase);
        al[1] = *(const unsigned*)(s1l[sb] + abase + 8*16);
        al[2] = *(const unsigned*)(s1l[sb] + abase + 8);
        al[3] = *(const unsigned*)(s1l[sb] + abase + 8*16 + 8);

        #pragma unroll
        for (int nf = 0; nf < 3; nf++) {
            int qc = m0 + nf*8 + g;
            int bbase = qc*16 + 2*tg;
            unsigned bh0 = *(const unsigned*)(s2h[sb] + bbase);
            unsigned bh1 = *(const unsigned*)(s2h[sb] + bbase + 8);
            unsigned bl0 = *(const unsigned*)(s2l[sb] + bbase);
            unsigned bl1 = *(const unsigned*)(s2l[sb] + bbase + 8);
            mma16816(acc[nf], ah, bh0, bh1);
            mma16816(acc[nf], ah, bl0, bl1);
            mma16816(acc[nf], al, bh0, bh1);
        }
    }

    int m0 = wid * 16;
    #pragma unroll
    for (int nf = 0; nf < 3; nf++) {
        #pragma unroll
        for (int q2 = 0; q2 < 4; q2++) {
            int pr = (q2 >= 2) ? 8 : 0;
            int col = 2*tg + (q2 & 1);
            int p = m0 + g + pr;
            int dx = nf*8 + col - g - pr;
            if (dx >= 0 && dx < 7) {
                float v = acc[nf][q2] * (1.f/128.f);
                v = (v >= 0.f) ? v : 0.01f*v;
                u16 h, l;
                bf16split(v, h, l);
                size_t o = ((size_t)b*HW + y*WW + p)*64 + dy*7 + dx;
                ch16[o] = h; cl16[o] = l;
            }
        }
    }
}

// ---------------- 4) tensor conv, 2-stage double-buffered ----------------
template<int CPAD, int COUT, int M, int MW, int NW, int OUTMODE>
__global__ void __launch_bounds__(256) k_convT(
    const u16* __restrict__ ah, const u16* __restrict__ al,
    const u16* __restrict__ wh, const u16* __restrict__ wl,
    const float* __restrict__ bias, float slope,
    float* __restrict__ outf, u16* __restrict__ oh, u16* __restrict__ ol)
{
    constexpr int MF = M / (16*MW);
    constexpr int NF = 128 / (8*NW);
    constexpr int BELEM = 3*130*16;
    constexpr int WELEM = 9*M*16;
    constexpr int STAGE = 2*BELEM + 2*WELEM;   // u16 elements per stage
    constexpr int NCH = CPAD / 16;

    extern __shared__ __align__(16) u16 sm16[];

    int tid = threadIdx.x;
    int row = blockIdx.x, ocg = blockIdx.y, b = blockIdx.z;
    int oc0 = ocg * M;
    int wid = tid >> 5, lane = tid & 31;
    int g = lane >> 2, tg = lane & 3;
    int wm = wid % MW, wn = wid / MW;

    float acc[MF][NF][4];
    #pragma unroll
    for (int mf = 0; mf < MF; mf++)
        #pragma unroll
        for (int nf = 0; nf < NF; nf++)
            #pragma unroll
            for (int q = 0; q < 4; q++) acc[mf][nf][q] = 0.f;

    const u16* abh = ah + (size_t)b*HW*CPAD;
    const u16* abl = al + (size_t)b*HW*CPAD;

    auto stage_ld = [&](int t, int sbuf) {
        u16* sBh = sm16 + sbuf*STAGE;
        u16* sBl = sBh + BELEM;
        u16* sWh = sBl + BELEM;
        u16* sWl = sWh + WELEM;
        int c0 = t*16;
        #pragma unroll 1
        for (int u = tid; u < 780; u += 256) {
            int half = u & 1;
            int pc = u >> 1;
            int c = pc % 130;
            int r = pc / 130;
            int gy = row - 1 + r, gx = c - 1;
            bool v = (unsigned)gy < 128u && (unsigned)gx < 128u;
            size_t go = v ? ((size_t)(gy*WW + gx)*CPAD + c0 + half*8) : 0;
            uint32_t so = (uint32_t)((pc*16 + half*8) * sizeof(u16));
            cpasync16(sptr(sBh) + so, abh + go, v);
            cpasync16(sptr(sBl) + so, abl + go, v);
        }
        #pragma unroll 1
        for (int u = tid; u < 9*M*2; u += 256) {
            int half = u & 1;
            int so16 = u >> 1;
            int s = so16 / M, oc = so16 - s*M;
            size_t go = ((size_t)(t*9 + s)*COUT + oc0 + oc)*16 + half*8;
            uint32_t so = (uint32_t)((so16*16 + half*8) * sizeof(u16));
            cpasync16(sptr(sWh) + so, wh + go, true);
            cpasync16(sptr(sWl) + so, wl + go, true);
        }
        cpasync_commit();
    };

    stage_ld(0, 0);

    #pragma unroll 1
    for (int t = 0; t < NCH; t++) {
        cpasync_wait_all();
        __syncthreads();
        if (t + 1 < NCH) stage_ld(t + 1, (t + 1) & 1);

        u16* sBh = sm16 + (t & 1)*STAGE;
        u16* sBl = sBh + BELEM;
        u16* sWh = sBl + BELEM;
        u16* sWl = sWh + WELEM;

        #pragma unroll
        for (int s = 0; s < 9; s++) {
            int ky = s / 3, kx = s % 3;
            unsigned ahf[MF][4], alf[MF][4];
            #pragma unroll
            for (int mf = 0; mf < MF; mf++) {
                int ocl = wm*MF*16 + mf*16 + g;
                int base = (s*M + ocl)*16 + 2*tg;
                ahf[mf][0] = *(const unsigned*)(sWh + base);
                ahf[mf][1] = *(const unsigned*)(sWh + base + 8*16);
                ahf[mf][2] = *(const unsigned*)(sWh + base + 8);
                ahf[mf][3] = *(const unsigned*)(sWh + base + 8*16 + 8);
                alf[mf][0] = *(const unsigned*)(sWl + base);
                alf[mf][1] = *(const unsigned*)(sWl + base + 8*16);
                alf[mf][2] = *(const unsigned*)(sWl + base + 8);
                alf[mf][3] = *(const unsigned*)(sWl + base + 8*16 + 8);
            }
            #pragma unroll
            for (int nf = 0; nf < NF; nf++) {
                int n = wn*NF*8 + nf*8 + g;
                int baseb = (ky*130 + kx + n)*16 + 2*tg;
                unsigned bh0 = *(const unsigned*)(sBh + baseb);
                unsigned bh1 = *(const unsigned*)(sBh + baseb + 8);
                unsigned bl0 = *(const unsigned*)(sBl + baseb);
                unsigned bl1 = *(const unsigned*)(sBl + baseb + 8);
                #pragma unroll
                for (int mf = 0; mf < MF; mf++) {
                    mma16816(acc[mf][nf], ahf[mf], bh0, bh1);
                    mma16816(acc[mf][nf], ahf[mf], bl0, bl1);
                    mma16816(acc[mf][nf], alf[mf], bh0, bh1);
                }
            }
        }
    }

    #pragma unroll
    for (int mf = 0; mf < MF; mf++) {
        int ocA = oc0 + wm*MF*16 + mf*16 + g;
        float bA = bias[ocA], bBv = bias[ocA + 8];
        #pragma unroll
        for (int nf = 0; nf < NF; nf++) {
            int col = wn*NF*8 + nf*8 + 2*tg;
            float v0 = acc[mf][nf][0] + bA,  v1 = acc[mf][nf][1] + bA;
            float v2 = acc[mf][nf][2] + bBv, v3 = acc[mf][nf][3] + bBv;
            v0 = (v0 >= 0.f) ? v0 : slope*v0;
            v1 = (v1 >= 0.f) ? v1 : slope*v1;
            v2 = (v2 >= 0.f) ? v2 : slope*v2;
            v3 = (v3 >= 0.f) ? v3 : slope*v3;
            if (OUTMODE == 0) {
                float* o = outf + ((size_t)(b*COUT + ocA))*HW + row*WW + col;
                float2 p0 = {v0, v1}, p1 = {v2, v3};
                *(float2*)o = p0;
                *(float2*)(o + (size_t)8*HW) = p1;
            } else {
                size_t p0 = ((size_t)b*HW + row*WW + col)*COUT;
                u16 h, l;
                bf16split(v0, h, l); oh[p0 + ocA] = h;            ol[p0 + ocA] = l;
                bf16split(v1, h, l); oh[p0 + COUT + ocA] = h;     ol[p0 + COUT + ocA] = l;
                bf16split(v2, h, l); oh[p0 + ocA + 8] = h;        ol[p0 + ocA + 8] = l;
                bf16split(v3, h, l); oh[p0 + COUT + ocA + 8] = h; ol[p0 + COUT + ocA + 8] = l;
            }
        }
    }
}

// ---------------- 5) conv4 (tiny, scalar) ----------------
__global__ void __launch_bounds__(256, 3) k_conv4(
    const float* __restrict__ in, const float* __restrict__ w,
    const float* __restrict__ bias, float* __restrict__ out,
    const float* __restrict__ addsrc)
{
    constexpr int CIN = 32, COUT = 2, KOC = 2, CH = 8;
    constexpr int TROW = 18, TCOL = 68;
    constexpr int TFILL = 18*66;
    constexpr int WCNT = CH*KOC*9;

    __shared__ __align__(16) float s_in[CH][TROW][TCOL];
    __shared__ __align__(16) ull s_w[WCNT];

    int tx = threadIdx.x, ty = threadIdx.y;
    int tid = ty*16 + tx;
    int bx = blockIdx.x*64, by = blockIdx.y*16;
    int b = blockIdx.z;
    int oc0 = 0;

    int soff[5], goff[5];
    bool inr[5], val[5];
    #pragma unroll
    for (int s = 0; s < 5; s++) {
        int i = tid + s*256;
        int r = i / 66, c = i - r*66;
        int gy = by - 1 + r, gx = bx - 1 + c;
        inr[s] = (i < TFILL);
        val[s] = inr[s] && (unsigned)gy < (unsigned)HH && (unsigned)gx < (unsigned)WW;
        soff[s] = r*TCOL + c;
        goff[s] = val[s] ? gy*WW + gx : 0;
    }

    const float* inb = in + (size_t)b*CIN*HW;
    float* sbase = &s_in[0][0][0];

    ull accA[KOC], accB[KOC];
    #pragma unroll
    for (int o = 0; o < KOC; o++) { accA[o] = 0ull; accB[o] = 0ull; }

    #pragma unroll 1
    for (int c0 = 0; c0 < CIN; c0 += CH) {
        __syncthreads();
        #pragma unroll 1
        for (int ci = 0; ci < CH; ci++) {
            const float* cp = inb + (size_t)(c0 + ci)*HW;
            float* sp = sbase + ci*(TROW*TCOL);
            #pragma unroll
            for (int s = 0; s < 5; s++)
                if (inr[s]) sp[soff[s]] = val[s] ? __ldg(cp + goff[s]) : 0.f;
        }
        if (tid < WCNT) {
            int ci = tid / (KOC*9), rem = tid % (KOC*9);
            int o = rem / 9, k = rem % 9;
            float wv = __ldg(w + ((size_t)(oc0 + o)*CIN + c0 + ci)*9 + k);
            s_w[tid] = pack2(wv, wv);
        }
        __syncthreads();

        #pragma unroll 1
        for (int ci = 0; ci < CH; ci++) {
            const ull* wp = s_w + ci*(KOC*9);
            const float* tb = sbase + ci*(TROW*TCOL) + ty*TCOL;
            #pragma unroll
            for (int ky = 0; ky < 3; ky++) {
                const ull* row = (const ull*)(tb + ky*TCOL);
                ull L0 = row[2*tx], L1 = row[2*tx+1], L2 = row[2*tx+2];
                float2 a0 = unpack2(L0), a1 = unpack2(L1), a2 = unpack2(L2);
                ull T1 = pack2(a0.y, a1.x);
                ull T3 = pack2(a1.y, a2.x);
                #pragma unroll
                for (int o = 0; o < KOC; o++) {
                    ull w0 = wp[o*9 + ky*3 + 0];
                    ull w1 = wp[o*9 + ky*3 + 1];
                    ull w2 = wp[o*9 + ky*3 + 2];
                    accA[o] = ffma2(L0, w0, accA[o]);
                    accA[o] = ffma2(T1, w1, accA[o]);
                    accA[o] = ffma2(L1, w2, accA[o]);
                    accB[o] = ffma2(L1, w0, accB[o]);
                    accB[o] = ffma2(T3, w1, accB[o]);
                    accB[o] = ffma2(L2, w2, accB[o]);
                }
            }
        }
    }

    int y = by + ty;
    int x = bx + 4*tx;
    #pragma unroll
    for (int o = 0; o < KOC; o++) {
        float2 vA = unpack2(accA[o]);
        float2 vB = unpack2(accB[o]);
        float bv = bias[oc0 + o];
        vA.x += bv; vA.y += bv; vB.x += bv; vB.y += bv;
        size_t off = ((size_t)(b*COUT + oc0 + o))*HW + y*WW + x;
        float2 r0 = *(const float2*)(addsrc + off);
        float2 r1 = *(const float2*)(addsrc + off + 2);
        vA.x += r0.x; vA.y += r0.y; vB.x += r1.x; vB.y += r1.y;
        *(float2*)(out + off)     = vA;
        *(float2*)(out + off + 2) = vB;
    }
}

// ---------------- launch ----------------
extern "C" void kernel_launch(void* const* d_in, const int* in_sizes, int n_in,
                              void* d_out, int out_size) {
    const float* feature1 = (const float*)d_in[0];
    const float* feature2 = (const float*)d_in[1];
    const float* flow     = (const float*)d_in[2];
    const float* up_w     = (const float*)d_in[3];
    const float* w1 = (const float*)d_in[4];  const float* b1 = (const float*)d_in[5];
    const float* w2 = (const float*)d_in[6];  const float* b2 = (const float*)d_in[7];
    const float* w3 = (const float*)d_in[8];  const float* b3 = (const float*)d_in[9];
    const float* w4 = (const float*)d_in[10]; const float* b4 = (const float*)d_in[11];
    float* out = (float*)d_out;

    float *p_flow_up, *p_h3;
    u16 *p_f1h, *p_f1l, *p_f2h, *p_f2l;
    u16 *p_c16h, *p_c16l, *p_h1h, *p_h1l, *p_h2h, *p_h2l;
    u16 *p_w1h, *p_w1l, *p_w2h, *p_w2l, *p_w3h, *p_w3l;
    cudaGetSymbolAddress((void**)&p_flow_up, g_flow_up);
    cudaGetSymbolAddress((void**)&p_h3,   g_h3);
    cudaGetSymbolAddress((void**)&p_f1h,  g_f1h);
    cudaGetSymbolAddress((void**)&p_f1l,  g_f1l);
    cudaGetSymbolAddress((void**)&p_f2h,  g_f2h);
    cudaGetSymbolAddress((void**)&p_f2l,  g_f2l);
    cudaGetSymbolAddress((void**)&p_c16h, g_c16h);
    cudaGetSymbolAddress((void**)&p_c16l, g_c16l);
    cudaGetSymbolAddress((void**)&p_h1h,  g_h1h);
    cudaGetSymbolAddress((void**)&p_h1l,  g_h1l);
    cudaGetSymbolAddress((void**)&p_h2h,  g_h2h);
    cudaGetSymbolAddress((void**)&p_h2l,  g_h2l);
    cudaGetSymbolAddress((void**)&p_w1h,  g_w1h);
    cudaGetSymbolAddress((void**)&p_w1l,  g_w1l);
    cudaGetSymbolAddress((void**)&p_w2h,  g_w2h);
    cudaGetSymbolAddress((void**)&p_w2l,  g_w2l);
    cudaGetSymbolAddress((void**)&p_w3h,  g_w3h);
    cudaGetSymbolAddress((void**)&p_w3l,  g_w3l);

    // double-buffered dynamic smem: 2 stages x (2*BELEM + 2*WELEM) u16
    constexpr int SM64 = 2 * (2*(3*130*16) + 2*(9*64*16)) * 2;  // 123648
    constexpr int SM32 = 2 * (2*(3*130*16) + 2*(9*32*16)) * 2;  // 86784
    cudaFuncSetAttribute(k_convT<64,128,64,2,4,1>, cudaFuncAttributeMaxDynamicSharedMemorySize, SM64);
    cudaFuncSetAttribute(k_convT<128,64,64,2,4,1>, cudaFuncAttributeMaxDynamicSharedMemorySize, SM64);
    cudaFuncSetAttribute(k_convT<64,32,32,1,8,0>,  cudaFuncAttributeMaxDynamicSharedMemorySize, SM32);

    k_upsample<<<(BB*2*HW + 255)/256, 256>>>(flow, up_w, p_flow_up);
    k_f1split<<<(BB*HW + 255)/256, 256>>>(feature1, p_f1h, p_f1l);
    k_warp<<<dim3(HH, BB, 4), 128>>>(feature2, p_flow_up, p_f2h, p_f2l);
    k_wsplit<49,128><<<(4*9*128*16 + 255)/256, 256>>>(w1, p_w1h, p_w1l);
    k_fillpad<<<(BB*HW*15 + 255)/256, 256>>>(p_c16h, p_c16l);
    k_corrT<<<dim3(HH, 7, BB), 256>>>(p_f1h, p_f1l, p_f2h, p_f2l, p_c16h, p_c16l);
    k_wsplit<128,64><<<(8*9*64*16 + 255)/256, 256>>>(w2, p_w2h, p_w2l);
    k_wsplit<64,32><<<(4*9*32*16 + 255)/256, 256>>>(w3, p_w3h, p_w3l);
    k_convT<64,128,64,2,4,1><<<dim3(HH, 2, BB), 256, SM64>>>(
        p_c16h, p_c16l, p_w1h, p_w1l, b1, 0.1f, nullptr, p_h1h, p_h1l);
    k_convT<128,64,64,2,4,1><<<dim3(HH, 1, BB), 256, SM64>>>(
        p_h1h, p_h1l, p_w2h, p_w2l, b2, 0.1f, nullptr, p_h2h, p_h2l);
    k_convT<64,32,32,1,8,0><<<dim3(HH, 1, BB), 256, SM32>>>(
        p_h2h, p_h2l, p_w3h, p_w3l, b3, 0.1f, p_h3, nullptr, nullptr);
    k_conv4<<<dim3(2, 8, BB), dim3(16, 16)>>>(p_h3, w4, b4, out, p_flow_up);
}

// round 16
// speedup vs baseline: 1.0461x; 1.0461x over previous
#include <cuda_runtime.h>
#include <cuda_bf16.h>
#include <cstdint>

#define BB 4
#define HH 128
#define WW 128
#define HW (HH*WW)

typedef unsigned long long ull;
typedef unsigned short u16;

// ---------------- scratch ----------------
__device__ float g_flow_up[BB*2*HW];
__device__ float g_h3[BB*32*HW];
__device__ u16 g_f1h[BB*HW*128], g_f1l[BB*HW*128];
__device__ u16 g_f2h[BB*HW*128], g_f2l[BB*HW*128];
__device__ u16 g_c16h[BB*HW*64],  g_c16l[BB*HW*64];
__device__ u16 g_h1h[BB*HW*128],  g_h1l[BB*HW*128];
__device__ u16 g_h2h[BB*HW*64],   g_h2l[BB*HW*64];
__device__ u16 g_w1h[4*9*128*16], g_w1l[4*9*128*16];
__device__ u16 g_w2h[8*9*64*16],  g_w2l[8*9*64*16];
__device__ u16 g_w3h[4*9*32*16],  g_w3l[4*9*32*16];

// ---------------- helpers ----------------
__device__ __forceinline__ ull ffma2(ull a, ull b, ull c) {
    ull d;
    asm("fma.rn.f32x2 %0, %1, %2, %3;" : "=l"(d) : "l"(a), "l"(b), "l"(c));
    return d;
}
__device__ __forceinline__ ull pack2(float lo, float hi) {
    ull r;
    asm("mov.b64 %0, {%1, %2};" : "=l"(r) : "f"(lo), "f"(hi));
    return r;
}
__device__ __forceinline__ float2 unpack2(ull v) {
    float2 r;
    asm("mov.b64 {%0, %1}, %2;" : "=f"(r.x), "=f"(r.y) : "l"(v));
    return r;
}
__device__ __forceinline__ void cpasync16(uint32_t saddr, const void* g, bool v) {
    int sz = v ? 16 : 0;
    asm volatile("cp.async.cg.shared.global [%0], [%1], 16, %2;"
                 :: "r"(saddr), "l"(g), "r"(sz));
}
__device__ __forceinline__ void cpasync_commit() {
    asm volatile("cp.async.commit_group;");
}
__device__ __forceinline__ void cpasync_wait_all() {
    asm volatile("cp.async.wait_group 0;");
}
__device__ __forceinline__ uint32_t sptr(const void* p) {
    return (uint32_t)__cvta_generic_to_shared(p);
}
__device__ __forceinline__ void mma16816(float* c, const unsigned* a, unsigned b0, unsigned b1) {
    asm volatile(
        "mma.sync.aligned.m16n8k16.row.col.f32.bf16.bf16.f32 "
        "{%0,%1,%2,%3}, {%4,%5,%6,%7}, {%8,%9}, {%0,%1,%2,%3};"
        : "+f"(c[0]), "+f"(c[1]), "+f"(c[2]), "+f"(c[3])
        : "r"(a[0]), "r"(a[1]), "r"(a[2]), "r"(a[3]), "r"(b0), "r"(b1));
}
__device__ __forceinline__ void bf16split(float v, u16& h, u16& l) {
    __nv_bfloat16 hb = __float2bfloat16(v);
    float hf = __bfloat162float(hb);
    __nv_bfloat16 lb = __float2bfloat16(v - hf);
    h = *(u16*)&hb;
    l = *(u16*)&lb;
}

// ---------------- 0a) zero pad channels 49..63 of corr16 ----------------
__global__ void k_fillpad(u16* __restrict__ h, u16* __restrict__ l) {
    int idx = blockIdx.x*256 + threadIdx.x;
    if (idx >= BB*HW*15) return;
    int c = 49 + idx % 15;
    int p = idx / 15;
    h[(size_t)p*64 + c] = 0;
    l[(size_t)p*64 + c] = 0;
}

// ---------------- 0b) weight pre-split ----------------
template<int CIN, int OC>
__global__ void k_wsplit(const float* __restrict__ w, u16* __restrict__ wh, u16* __restrict__ wl) {
    constexpr int NCH = (CIN + 15)/16;
    int idx = blockIdx.x*256 + threadIdx.x;
    if (idx >= NCH*9*OC*16) return;
    int k  = idx & 15;
    int t2 = idx >> 4;
    int oc = t2 % OC;
    int t3 = t2 / OC;
    int s  = t3 % 9;
    int t  = t3 / 9;
    int ci = t*16 + k;
    float v = (ci < CIN) ? __ldg(w + ((size_t)oc*CIN + ci)*9 + s) : 0.f;
    u16 h, l;
    bf16split(v, h, l);
    wh[idx] = h; wl[idx] = l;
}

// ---------------- 0c) feature1 split (uint4-packed stores) ----------------
__global__ void k_f1split(const float* __restrict__ f, u16* __restrict__ fh, u16* __restrict__ fl) {
    int p = blockIdx.x*256 + threadIdx.x;
    if (p >= BB*HW) return;
    int b = p >> 14, pix = p & (HW-1);
    const float* src = f + (size_t)b*128*HW + pix;
    uint4* dh = (uint4*)(fh + (size_t)p*128);
    uint4* dl = (uint4*)(fl + (size_t)p*128);
    #pragma unroll 1
    for (int cg = 0; cg < 16; cg++) {
        u16 hh[8], ll[8];
        #pragma unroll
        for (int j = 0; j < 8; j++)
            bf16split(__ldg(src + (size_t)(cg*8 + j)*HW), hh[j], ll[j]);
        dh[cg] = *(uint4*)hh;
        dl[cg] = *(uint4*)ll;
    }
}

// ---------------- 1) grouped ConvTranspose2d ----------------
__global__ void k_upsample(const float* __restrict__ flow, const float* __restrict__ up_w,
                           float* __restrict__ out) {
    int idx = blockIdx.x * blockDim.x + threadIdx.x;
    if (idx >= BB*2*HW) return;
    int x = idx & 127;
    int y = (idx >> 7) & 127;
    int g = (idx >> 14) & 1;
    int b = idx >> 15;
    const float* fin = flow + (b*2 + g) * 64 * 64;
    const float* wg  = up_w + g * 16;
    float acc = 0.f;
    #pragma unroll
    for (int ky = 0; ky < 4; ky++) {
        int t = y + 1 - ky;
        if (t & 1) continue;
        int i = t >> 1;
        if ((unsigned)i >= 64u) continue;
        #pragma unroll
        for (int kx = 0; kx < 4; kx++) {
            int s = x + 1 - kx;
            if (s & 1) continue;
            int j = s >> 1;
            if ((unsigned)j >= 64u) continue;
            acc += fin[i*64 + j] * wg[ky*4 + kx];
        }
    }
    out[idx] = acc;
}

// ---------------- 2) warp feature2 -> channel-last bf16 hi/lo ----------------
__device__ __forceinline__ float reflectf(float v, float n) {
    float t = fmodf(fabsf(v), 2.0f * n);
    return n - fabsf(t - n);
}

__global__ void k_warp(const float* __restrict__ f2, const float* __restrict__ fu,
                       u16* __restrict__ fh, u16* __restrict__ fl) {
    int x = threadIdx.x;
    int y = blockIdx.x;
    int b = blockIdx.y;
    int c0 = blockIdx.z * 32;

    const float* fub = fu + (size_t)b*2*HW;
    float u0 = fub[y*WW + x];
    float u1 = fub[HW + y*WW + x];

    float fx = reflectf((float)x + 0.05f*u1, 127.f);
    float fy = reflectf((float)y + 0.05f*u0, 127.f);

    float x0f = floorf(fx), y0f = floorf(fy);
    float wx = fx - x0f, wy = fy - y0f;
    int x0 = min(max((int)x0f, 0), 127);
    int x1 = min(x0 + 1, 127);
    int y0 = min(max((int)y0f, 0), 127);
    int y1 = min(y0 + 1, 127);
    float w00 = (1.f-wx)*(1.f-wy), w01 = wx*(1.f-wy);
    float w10 = (1.f-wx)*wy,       w11 = wx*wy;

    int o00 = y0*WW + x0, o01 = y0*WW + x1, o10 = y1*WW + x0, o11 = y1*WW + x1;
    const float* fb = f2 + (size_t)b*128*HW;
    int po = y*WW + x;
    uint4* dh = (uint4*)(fh + ((size_t)b*HW + po)*128 + c0);
    uint4* dl = (uint4*)(fl + ((size_t)b*HW + po)*128 + c0);
    #pragma unroll 1
    for (int cg = 0; cg < 4; cg++) {
        u16 hh[8], ll[8];
        #pragma unroll
        for (int j = 0; j < 8; j++) {
            const float* fc = fb + (size_t)(c0 + cg*8 + j)*HW;
            float v = w00*fc[o00] + w01*fc[o01] + w10*fc[o10] + w11*fc[o11];
            bf16split(v, hh[j], ll[j]);
        }
        dh[cg] = *(uint4*)hh;
        dl[cg] = *(uint4*)ll;
    }
}

// ---------------- 3) MMA cost volume, 2-stage double-buffered ----------------
__global__ void __launch_bounds__(256) k_corrT(
    const u16* __restrict__ f1h_, const u16* __restrict__ f1l_,
    const u16* __restrict__ f2h_, const u16* __restrict__ f2l_,
    u16* __restrict__ ch16, u16* __restrict__ cl16)
{
    __shared__ __align__(16) u16 s1h[2][128*16], s1l[2][128*16];
    __shared__ __align__(16) u16 s2h[2][136*16], s2l[2][136*16];

    int tid = threadIdx.x;
    int y = blockIdx.x, dy = blockIdx.y, b = blockIdx.z;
    int wid = tid >> 5, lane = tid & 31;
    int g = lane >> 2, tg = lane & 3;
    int gy = y + dy - 3;
    bool rowok = (unsigned)gy < 128u;

    float acc[3][4];
    #pragma unroll
    for (int nf = 0; nf < 3; nf++)
        #pragma unroll
        for (int q = 0; q < 4; q++) acc[nf][q] = 0.f;

    size_t f1base = ((size_t)b*HW + y*WW)*128;
    size_t f2base = rowok ? ((size_t)b*HW + gy*WW)*128 : 0;

    auto stage = [&](int kc, int sb) {
        #pragma unroll
        for (int u = tid; u < 512; u += 256) {
            int half = u & 1;
            int px = (u >> 1) & 127;
            int arr = u >> 8;
            const u16* src = (arr ? f1l_ : f1h_) + f1base + (size_t)px*128 + kc*16 + half*8;
            u16* dst = (arr ? s1l[sb] : s1h[sb]) + px*16 + half*8;
            cpasync16(sptr(dst), src, true);
        }
        #pragma unroll
        for (int u = tid; u < 544; u += 256) {
            int half = u & 1;
            int idx = u >> 1;
            int qc = idx % 136;
            int arr = idx / 136;
            int q = qc - 3;
            bool v = rowok && (unsigned)q < 128u;
            const u16* src = (arr ? f2l_ : f2h_) + (v ? f2base + (size_t)q*128 + kc*16 + half*8 : 0);
            u16* dst = (arr ? s2l[sb] : s2h[sb]) + qc*16 + half*8;
            cpasync16(sptr(dst), src, v);
        }
        cpasync_commit();
    };

    stage(0, 0);

    #pragma unroll 1
    for (int kc = 0; kc < 8; kc++) {
        cpasync_wait_all();
        __syncthreads();
        if (kc + 1 < 8) stage(kc + 1, (kc + 1) & 1);
        int sb = kc & 1;

        int m0 = wid * 16;
        int abase = (m0 + g)*16 + 2*tg;
        unsigned ah[4], al[4];
        ah[0] = *(const unsigned*)(s1h[sb] + abase);
        ah[1] = *(const unsigned*)(s1h[sb] + abase + 8*16);
        ah[2] = *(const unsigned*)(s1h[sb] + abase + 8);
        ah[3] = *(const unsigned*)(s1h[sb] + abase + 8*16 + 8);
        al[0] = *(const unsigned*)(s1l[sb] + abase);
        al[1] = *(const unsigned*)(s1l[sb] + abase + 8*16);
        al[2] = *(const unsigned*)(s1l[sb] + abase + 8);
        al[3] = *(const unsigned*)(s1l[sb] + abase + 8*16 + 8);

        #pragma unroll
        for (int nf = 0; nf < 3; nf++) {
            int qc = m0 + nf*8 + g;
            int bbase = qc*16 + 2*tg;
            unsigned bh0 = *(const unsigned*)(s2h[sb] + bbase);
            unsigned bh1 = *(const unsigned*)(s2h[sb] + bbase + 8);
            unsigned bl0 = *(const unsigned*)(s2l[sb] + bbase);
            unsigned bl1 = *(const unsigned*)(s2l[sb] + bbase + 8);
            mma16816(acc[nf], ah, bh0, bh1);
            mma16816(acc[nf], ah, bl0, bl1);
            mma16816(acc[nf], al, bh0, bh1);
        }
    }

    int m0 = wid * 16;
    #pragma unroll
    for (int nf = 0; nf < 3; nf++) {
        #pragma unroll
        for (int q2 = 0; q2 < 4; q2++) {
            int pr = (q2 >= 2) ? 8 : 0;
            int col = 2*tg + (q2 & 1);
            int p = m0 + g + pr;
            int dx = nf*8 + col - g - pr;
            if (dx >= 0 && dx < 7) {
                float v = acc[nf][q2] * (1.f/128.f);
                v = (v >= 0.f) ? v : 0.01f*v;
                u16 h, l;
                bf16split(v, h, l);
                size_t o = ((size_t)b*HW + y*WW + p)*64 + dy*7 + dx;
                ch16[o] = h; cl16[o] = l;
            }
        }
    }
}

// ---------------- 4) tensor conv: single-buffer (R12 best) ----------------
template<int CPAD, int COUT, int M, int MW, int NW, int OUTMODE>
__global__ void __launch_bounds__(256) k_convT(
    const u16* __restrict__ ah, const u16* __restrict__ al,
    const u16* __restrict__ wh, const u16* __restrict__ wl,
    const float* __restrict__ bias, float slope,
    float* __restrict__ outf, u16* __restrict__ oh, u16* __restrict__ ol)
{
    constexpr int MF = M / (16*MW);
    constexpr int NF = 128 / (8*NW);
    constexpr int BELEM = 3*130*16;
    constexpr int WELEM = 9*M*16;

    extern __shared__ __align__(16) u16 sm16[];
    u16* sBh = sm16;
    u16* sBl = sBh + BELEM;
    u16* sWh = sBl + BELEM;
    u16* sWl = sWh + WELEM;

    int tid = threadIdx.x;
    int row = blockIdx.x, ocg = blockIdx.y, b = blockIdx.z;
    int oc0 = ocg * M;
    int wid = tid >> 5, lane = tid & 31;
    int g = lane >> 2, tg = lane & 3;
    int wm = wid % MW, wn = wid / MW;

    float acc[MF][NF][4];
    #pragma unroll
    for (int mf = 0; mf < MF; mf++)
        #pragma unroll
        for (int nf = 0; nf < NF; nf++)
            #pragma unroll
            for (int q = 0; q < 4; q++) acc[mf][nf][q] = 0.f;

    const u16* abh = ah + (size_t)b*HW*CPAD;
    const u16* abl = al + (size_t)b*HW*CPAD;

    #pragma unroll 1
    for (int c0 = 0; c0 < CPAD; c0 += 16) {
        int t = c0 >> 4;
        __syncthreads();
        #pragma unroll 1
        for (int u = tid; u < 780; u += 256) {
            int half = u & 1;
            int pc = u >> 1;
            int c = pc % 130;
            int r = pc / 130;
            int gy = row - 1 + r, gx = c - 1;
            bool v = (unsigned)gy < 128u && (unsigned)gx < 128u;
            size_t go = v ? ((size_t)(gy*WW + gx)*CPAD + c0 + half*8) : 0;
            uint32_t so = (uint32_t)((pc*16 + half*8) * sizeof(u16));
            cpasync16(sptr(sBh) + so, abh + go, v);
            cpasync16(sptr(sBl) + so, abl + go, v);
        }
        #pragma unroll 1
        for (int u = tid; u < 9*M*2; u += 256) {
            int half = u & 1;
            int so16 = u >> 1;
            int s = so16 / M, oc = so16 - s*M;
            size_t go = ((size_t)(t*9 + s)*COUT + oc0 + oc)*16 + half*8;
            uint32_t so = (uint32_t)((so16*16 + half*8) * sizeof(u16));
            cpasync16(sptr(sWh) + so, wh + go, true);
            cpasync16(sptr(sWl) + so, wl + go, true);
        }
        cpasync_commit();
        cpasync_wait_all();
        __syncthreads();

        #pragma unroll
        for (int s = 0; s < 9; s++) {
            int ky = s / 3, kx = s % 3;
            unsigned ahf[MF][4], alf[MF][4];
            #pragma unroll
            for (int mf = 0; mf < MF; mf++) {
                int ocl = wm*MF*16 + mf*16 + g;
                int base = (s*M + ocl)*16 + 2*tg;
                ahf[mf][0] = *(const unsigned*)(sWh + base);
                ahf[mf][1] = *(const unsigned*)(sWh + base + 8*16);
                ahf[mf][2] = *(const unsigned*)(sWh + base + 8);
                ahf[mf][3] = *(const unsigned*)(sWh + base + 8*16 + 8);
                alf[mf][0] = *(const unsigned*)(sWl + base);
                alf[mf][1] = *(const unsigned*)(sWl + base + 8*16);
                alf[mf][2] = *(const unsigned*)(sWl + base + 8);
                alf[mf][3] = *(const unsigned*)(sWl + base + 8*16 + 8);
            }
            #pragma unroll
            for (int nf = 0; nf < NF; nf++) {
                int n = wn*NF*8 + nf*8 + g;
                int baseb = (ky*130 + kx + n)*16 + 2*tg;
                unsigned bh0 = *(const unsigned*)(sBh + baseb);
                unsigned bh1 = *(const unsigned*)(sBh + baseb + 8);
                unsigned bl0 = *(const unsigned*)(sBl + baseb);
                unsigned bl1 = *(const unsigned*)(sBl + baseb + 8);
                #pragma unroll
                for (int mf = 0; mf < MF; mf++) {
                    mma16816(acc[mf][nf], ahf[mf], bh0, bh1);
                    mma16816(acc[mf][nf], ahf[mf], bl0, bl1);
                    mma16816(acc[mf][nf], alf[mf], bh0, bh1);
                }
            }
        }
    }

    #pragma unroll
    for (int mf = 0; mf < MF; mf++) {
        int ocA = oc0 + wm*MF*16 + mf*16 + g;
        float bA = bias[ocA], bBv = bias[ocA + 8];
        #pragma unroll
        for (int nf = 0; nf < NF; nf++) {
            int col = wn*NF*8 + nf*8 + 2*tg;
            float v0 = acc[mf][nf][0] + bA,  v1 = acc[mf][nf][1] + bA;
            float v2 = acc[mf][nf][2] + bBv, v3 = acc[mf][nf][3] + bBv;
            v0 = (v0 >= 0.f) ? v0 : slope*v0;
            v1 = (v1 >= 0.f) ? v1 : slope*v1;
            v2 = (v2 >= 0.f) ? v2 : slope*v2;
            v3 = (v3 >= 0.f) ? v3 : slope*v3;
            if (OUTMODE == 0) {
                float* o = outf + ((size_t)(b*COUT + ocA))*HW + row*WW + col;
                float2 p0 = {v0, v1}, p1 = {v2, v3};
                *(float2*)o = p0;
                *(float2*)(o + (size_t)8*HW) = p1;
            } else {
                size_t p0 = ((size_t)b*HW + row*WW + col)*COUT;
                u16 h, l;
                bf16split(v0, h, l); oh[p0 + ocA] = h;            ol[p0 + ocA] = l;
                bf16split(v1, h, l); oh[p0 + COUT + ocA] = h;     ol[p0 + COUT + ocA] = l;
                bf16split(v2, h, l); oh[p0 + ocA + 8] = h;        ol[p0 + ocA + 8] = l;
                bf16split(v3, h, l); oh[p0 + COUT + ocA + 8] = h; ol[p0 + COUT + ocA + 8] = l;
            }
        }
    }
}

// ---------------- 5) conv4 (tiny, scalar) ----------------
__global__ void __launch_bounds__(256, 3) k_conv4(
    const float* __restrict__ in, const float* __restrict__ w,
    const float* __restrict__ bias, float* __restrict__ out,
    const float* __restrict__ addsrc)
{
    constexpr int CIN = 32, COUT = 2, KOC = 2, CH = 8;
    constexpr int TROW = 18, TCOL = 68;
    constexpr int TFILL = 18*66;
    constexpr int WCNT = CH*KOC*9;

    __shared__ __align__(16) float s_in[CH][TROW][TCOL];
    __shared__ __align__(16) ull s_w[WCNT];

    int tx = threadIdx.x, ty = threadIdx.y;
    int tid = ty*16 + tx;
    int bx = blockIdx.x*64, by = blockIdx.y*16;
    int b = blockIdx.z;
    int oc0 = 0;

    int soff[5], goff[5];
    bool inr[5], val[5];
    #pragma unroll
    for (int s = 0; s < 5; s++) {
        int i = tid + s*256;
        int r = i / 66, c = i - r*66;
        int gy = by - 1 + r, gx = bx - 1 + c;
        inr[s] = (i < TFILL);
        val[s] = inr[s] && (unsigned)gy < (unsigned)HH && (unsigned)gx < (unsigned)WW;
        soff[s] = r*TCOL + c;
        goff[s] = val[s] ? gy*WW + gx : 0;
    }

    const float* inb = in + (size_t)b*CIN*HW;
    float* sbase = &s_in[0][0][0];

    ull accA[KOC], accB[KOC];
    #pragma unroll
    for (int o = 0; o < KOC; o++) { accA[o] = 0ull; accB[o] = 0ull; }

    #pragma unroll 1
    for (int c0 = 0; c0 < CIN; c0 += CH) {
        __syncthreads();
        #pragma unroll 1
        for (int ci = 0; ci < CH; ci++) {
            const float* cp = inb + (size_t)(c0 + ci)*HW;
            float* sp = sbase + ci*(TROW*TCOL);
            #pragma unroll
            for (int s = 0; s < 5; s++)
                if (inr[s]) sp[soff[s]] = val[s] ? __ldg(cp + goff[s]) : 0.f;
        }
        if (tid < WCNT) {
            int ci = tid / (KOC*9), rem = tid % (KOC*9);
            int o = rem / 9, k = rem % 9;
            float wv = __ldg(w + ((size_t)(oc0 + o)*CIN + c0 + ci)*9 + k);
            s_w[tid] = pack2(wv, wv);
        }
        __syncthreads();

        #pragma unroll 1
        for (int ci = 0; ci < CH; ci++) {
            const ull* wp = s_w + ci*(KOC*9);
            const float* tb = sbase + ci*(TROW*TCOL) + ty*TCOL;
            #pragma unroll
            for (int ky = 0; ky < 3; ky++) {
                const ull* row = (const ull*)(tb + ky*TCOL);
                ull L0 = row[2*tx], L1 = row[2*tx+1], L2 = row[2*tx+2];
                float2 a0 = unpack2(L0), a1 = unpack2(L1), a2 = unpack2(L2);
                ull T1 = pack2(a0.y, a1.x);
                ull T3 = pack2(a1.y, a2.x);
                #pragma unroll
                for (int o = 0; o < KOC; o++) {
                    ull w0 = wp[o*9 + ky*3 + 0];
                    ull w1 = wp[o*9 + ky*3 + 1];
                    ull w2 = wp[o*9 + ky*3 + 2];
                    accA[o] = ffma2(L0, w0, accA[o]);
                    accA[o] = ffma2(T1, w1, accA[o]);
                    accA[o] = ffma2(L1, w2, accA[o]);
                    accB[o] = ffma2(L1, w0, accB[o]);
                    accB[o] = ffma2(T3, w1, accB[o]);
                    accB[o] = ffma2(L2, w2, accB[o]);
                }
            }
        }
    }

    int y = by + ty;
    int x = bx + 4*tx;
    #pragma unroll
    for (int o = 0; o < KOC; o++) {
        float2 vA = unpack2(accA[o]);
        float2 vB = unpack2(accB[o]);
        float bv = bias[oc0 + o];
        vA.x += bv; vA.y += bv; vB.x += bv; vB.y += bv;
        size_t off = ((size_t)(b*COUT + oc0 + o))*HW + y*WW + x;
        float2 r0 = *(const float2*)(addsrc + off);
        float2 r1 = *(const float2*)(addsrc + off + 2);
        vA.x += r0.x; vA.y += r0.y; vB.x += r1.x; vB.y += r1.y;
        *(float2*)(out + off)     = vA;
        *(float2*)(out + off + 2) = vB;
    }
}

// ---------------- launch ----------------
extern "C" void kernel_launch(void* const* d_in, const int* in_sizes, int n_in,
                              void* d_out, int out_size) {
    const float* feature1 = (const float*)d_in[0];
    const float* feature2 = (const float*)d_in[1];
    const float* flow     = (const float*)d_in[2];
    const float* up_w     = (const float*)d_in[3];
    const float* w1 = (const float*)d_in[4];  const float* b1 = (const float*)d_in[5];
    const float* w2 = (const float*)d_in[6];  const float* b2 = (const float*)d_in[7];
    const float* w3 = (const float*)d_in[8];  const float* b3 = (const float*)d_in[9];
    const float* w4 = (const float*)d_in[10]; const float* b4 = (const float*)d_in[11];
    float* out = (float*)d_out;

    float *p_flow_up, *p_h3;
    u16 *p_f1h, *p_f1l, *p_f2h, *p_f2l;
    u16 *p_c16h, *p_c16l, *p_h1h, *p_h1l, *p_h2h, *p_h2l;
    u16 *p_w1h, *p_w1l, *p_w2h, *p_w2l, *p_w3h, *p_w3l;
    cudaGetSymbolAddress((void**)&p_flow_up, g_flow_up);
    cudaGetSymbolAddress((void**)&p_h3,   g_h3);
    cudaGetSymbolAddress((void**)&p_f1h,  g_f1h);
    cudaGetSymbolAddress((void**)&p_f1l,  g_f1l);
    cudaGetSymbolAddress((void**)&p_f2h,  g_f2h);
    cudaGetSymbolAddress((void**)&p_f2l,  g_f2l);
    cudaGetSymbolAddress((void**)&p_c16h, g_c16h);
    cudaGetSymbolAddress((void**)&p_c16l, g_c16l);
    cudaGetSymbolAddress((void**)&p_h1h,  g_h1h);
    cudaGetSymbolAddress((void**)&p_h1l,  g_h1l);
    cudaGetSymbolAddress((void**)&p_h2h,  g_h2h);
    cudaGetSymbolAddress((void**)&p_h2l,  g_h2l);
    cudaGetSymbolAddress((void**)&p_w1h,  g_w1h);
    cudaGetSymbolAddress((void**)&p_w1l,  g_w1l);
    cudaGetSymbolAddress((void**)&p_w2h,  g_w2h);
    cudaGetSymbolAddress((void**)&p_w2l,  g_w2l);
    cudaGetSymbolAddress((void**)&p_w3h,  g_w3h);
    cudaGetSymbolAddress((void**)&p_w3l,  g_w3l);

    // single-buffer convT smem (R12 best)
    constexpr int SM64 = (2*(3*130*16) + 2*(9*64*16)) * 2;  // 61824
    constexpr int SM32 = (2*(3*130*16) + 2*(9*32*16)) * 2;  // 43392
    cudaFuncSetAttribute(k_convT<64,128,64,2,4,1>, cudaFuncAttributeMaxDynamicSharedMemorySize, SM64);
    cudaFuncSetAttribute(k_convT<128,64,64,2,4,1>, cudaFuncAttributeMaxDynamicSharedMemorySize, SM64);
    cudaFuncSetAttribute(k_convT<64,32,32,1,8,0>,  cudaFuncAttributeMaxDynamicSharedMemorySize, SM32);

    k_upsample<<<(BB*2*HW + 255)/256, 256>>>(flow, up_w, p_flow_up);
    k_f1split<<<(BB*HW + 255)/256, 256>>>(feature1, p_f1h, p_f1l);
    k_warp<<<dim3(HH, BB, 4), 128>>>(feature2, p_flow_up, p_f2h, p_f2l);
    k_wsplit<49,128><<<(4*9*128*16 + 255)/256, 256>>>(w1, p_w1h, p_w1l);
    k_fillpad<<<(BB*HW*15 + 255)/256, 256>>>(p_c16h, p_c16l);
    k_corrT<<<dim3(HH, 7, BB), 256>>>(p_f1h, p_f1l, p_f2h, p_f2l, p_c16h, p_c16l);
    k_wsplit<128,64><<<(8*9*64*16 + 255)/256, 256>>>(w2, p_w2h, p_w2l);
    k_wsplit<64,32><<<(4*9*32*16 + 255)/256, 256>>>(w3, p_w3h, p_w3l);
    k_convT<64,128,64,2,4,1><<<dim3(HH, 2, BB), 256, SM64>>>(
        p_c16h, p_c16l, p_w1h, p_w1l, b1, 0.1f, nullptr, p_h1h, p_h1l);
    k_convT<128,64,64,2,4,1><<<dim3(HH, 1, BB), 256, SM64>>>(
        p_h1h, p_h1l, p_w2h, p_w2l, b2, 0.1f, nullptr, p_h2h, p_h2l);
    k_convT<64,32,32,1,8,0><<<dim3(HH, 1, BB), 256, SM32>>>(
        p_h2h, p_h2l, p_w3h, p_w3l, b3, 0.1f, p_h3, nullptr, nullptr);
    k_conv4<<<dim3(2, 8, BB), dim3(16, 16)>>>(p_h3, w4, b4, out, p_flow_up);
}